// round 7
// baseline (speedup 1.0000x reference)
#include <cuda_runtime.h>
#include <stdint.h>

// Problem constants
#define BB 32
#define TT 64
#define NN 4096   // TT*TT
#define KK 80
#define DD 512

// Scratch for top-k flat indices (no device allocation allowed -> __device__ global)
__device__ int g_topk_idx[BB * KK];

// ---------------------------------------------------------------------------
// Kernel 1: per-batch stable descending top-K via full bitonic sort of 4096
// 44-bit keys: (orderable float bits << 12) | (4095 - flat_idx).
// For equal values, larger (4095-idx) sorts first => smaller idx first,
// matching jax.lax.top_k's stable tie-break.
// ---------------------------------------------------------------------------
__global__ __launch_bounds__(512, 2)
void topk_kernel(const float* __restrict__ logit) {
    __shared__ unsigned long long keys[NN];  // 32 KB

    const int b = blockIdx.x;
    const int t = threadIdx.x;
    const float* base = logit + (size_t)b * NN;

    // Encode keys
    #pragma unroll
    for (int i = t; i < NN; i += 512) {
        float v = base[i];
        unsigned int u;
        if (v == 0.0f) {
            u = 0u;  // masked to -inf (smallest possible)
        } else {
            u = __float_as_uint(v);
            u = (u & 0x80000000u) ? ~u : (u | 0x80000000u);  // monotone map
        }
        keys[i] = ((unsigned long long)u << 12) | (unsigned int)(NN - 1 - i);
    }
    __syncthreads();

    // Bitonic sort, descending overall
    for (int k = 2; k <= NN; k <<= 1) {
        for (int j = k >> 1; j > 0; j >>= 1) {
            #pragma unroll
            for (int i = t; i < NN; i += 512) {
                int ixj = i ^ j;
                if (ixj > i) {
                    unsigned long long a = keys[i];
                    unsigned long long c = keys[ixj];
                    bool desc = ((i & k) == 0);
                    bool swap = desc ? (a < c) : (a > c);
                    if (swap) { keys[i] = c; keys[ixj] = a; }
                }
            }
            __syncthreads();
        }
    }

    // Top-K flat indices (sorted descending by score already)
    if (t < KK) {
        int idx = NN - 1 - (int)(keys[t] & 0xFFFu);
        g_topk_idx[b * KK + t] = idx;
    }
}

// ---------------------------------------------------------------------------
// Kernel 2: gathers. One block per (b, k) proposal.
// Output layout (f32, concatenated flattened):
//   [0)                    prop_lists    B*K*D
//   [B*K*D)                pred_s_e      B*K*2   (ints cast to float)
//   [B*K*D + B*K*2)        offset_gt     B*K*2
//   [B*K*D + B*K*4)        pred_score    B*K
// ---------------------------------------------------------------------------
__global__ __launch_bounds__(128)
void gather_kernel(const float* __restrict__ map2d,
                   const float* __restrict__ offset_gt,
                   const float* __restrict__ tmap,
                   float* __restrict__ out) {
    const int blk = blockIdx.x;            // 0 .. B*K-1
    const int b = blk / KK;
    const int t = threadIdx.x;             // 128 threads

    const int idx = g_topk_idx[blk];
    const int row = idx >> 6;              // idx / T
    const int col = idx & 63;              // idx % T

    // map2d row copy: 512 f32 = 128 float4 -> one per thread
    const size_t cell = ((size_t)(b * TT + row) * TT + col);
    const float4* src = (const float4*)(map2d + cell * DD);
    float4* dst = (float4*)(out + (size_t)blk * DD);
    dst[t] = src[t];

    if (t == 0) {
        const size_t O1 = (size_t)BB * KK * DD;          // pred_s_e
        const size_t O2 = O1 + (size_t)BB * KK * 2;      // offset_gt_list
        const size_t O3 = O2 + (size_t)BB * KK * 2;      // pred_score

        out[O1 + blk * 2 + 0] = (float)row;
        out[O1 + blk * 2 + 1] = (float)(col + 1);

        const float* og = offset_gt + cell * 2;
        out[O2 + blk * 2 + 0] = og[0];
        out[O2 + blk * 2 + 1] = og[1];

        out[O3 + blk] = tmap[(size_t)b * NN + idx];
    }
}

extern "C" void kernel_launch(void* const* d_in, const int* in_sizes, int n_in,
                              void* d_out, int out_size) {
    const float* selection_logit = (const float*)d_in[0];
    const float* map2d           = (const float*)d_in[1];
    const float* offset_gt       = (const float*)d_in[2];
    const float* tmap            = (const float*)d_in[3];
    float* out = (float*)d_out;

    topk_kernel<<<BB, 512>>>(selection_logit);
    gather_kernel<<<BB * KK, 128>>>(map2d, offset_gt, tmap, out);
}

// round 8
// speedup vs baseline: 1.7859x; 1.7859x over previous
#include <cuda_runtime.h>
#include <stdint.h>

#define BB 32
#define TT 64
#define NN 4096   // TT*TT
#define KK 80
#define DD 512

// Single fused kernel: per-batch exact top-80 via radix select (keys in
// registers), tiny bitonic sort of the 80 winners, then the block gathers
// its own rows + scalars. One block per batch.
__global__ __launch_bounds__(512, 1)
void proposal_kernel(const float* __restrict__ logit,
                     const float* __restrict__ map2d,
                     const float* __restrict__ offset_gt,
                     const float* __restrict__ tmap,
                     float* __restrict__ out) {
    __shared__ unsigned int       hist[256];
    __shared__ unsigned int       s_suf[257];   // suffix sums; s_suf[256] = 0
    __shared__ unsigned int       s_warp[8];
    __shared__ unsigned long long cand[128];
    __shared__ int                s_idx[KK];
    __shared__ unsigned int       s_cnt;
    __shared__ int                s_bin;
    __shared__ unsigned int       s_high;

    const int b    = blockIdx.x;
    const int t    = threadIdx.x;
    const int lane = t & 31;
    const int warp = t >> 5;

    // ---- encode 8 keys per thread into registers --------------------------
    // key = (orderable float bits << 12) | (4095 - idx); all keys distinct,
    // equal values break ties toward smaller idx (matches jax.lax.top_k).
    unsigned long long key[8];
    const float* base = logit + (size_t)b * NN;
#pragma unroll
    for (int e = 0; e < 8; e++) {
        int i = t + e * 512;
        float v = base[i];
        unsigned int u;
        if (v == 0.0f) {
            u = 0u;  // masked (-inf)
        } else {
            u = __float_as_uint(v);
            u = (u & 0x80000000u) ? ~u : (u | 0x80000000u);  // monotone map
        }
        key[e] = ((unsigned long long)u << 12) | (unsigned int)(NN - 1 - i);
    }

    // ---- exact radix select of the K-th largest key (8 bits x 6 passes) ---
    unsigned long long pref = 0;   // determined high bits so far (right-aligned)
    unsigned int remK = KK;        // rank still to locate within matching set

    for (int pass = 0; pass < 6; pass++) {
        const int shift = 40 - pass * 8;

        if (t < 256) hist[t] = 0;
        if (t == 256) s_suf[256] = 0;
        __syncthreads();

        // warp-aggregated histogram of matching keys' current digit
#pragma unroll
        for (int e = 0; e < 8; e++) {
            bool m = (key[e] >> (shift + 8)) == pref;
            unsigned int d = (unsigned int)(key[e] >> shift) & 255u;
            unsigned int mv = __ballot_sync(0xffffffffu, m);
            if (m) {
                unsigned int peers = __match_any_sync(mv, d);
                if (lane == (__ffs(peers) - 1))
                    atomicAdd(&hist[d], (unsigned int)__popc(peers));
            }
        }
        __syncthreads();

        // inclusive suffix scan of hist: s_suf[d] = sum_{j>=d} hist[j]
        unsigned int s = (t < 256) ? hist[t] : 0u;
#pragma unroll
        for (int off = 1; off < 32; off <<= 1) {
            unsigned int o = __shfl_down_sync(0xffffffffu, s, off);
            if (lane + off < 32) s += o;
        }
        if (t < 256 && lane == 0) s_warp[warp] = s;  // warp suffix totals
        __syncthreads();
        if (t < 256) {
            unsigned int hi = 0;
            for (int w2 = warp + 1; w2 < 8; w2++) hi += s_warp[w2];
            s_suf[t] = s + hi;
        }
        __syncthreads();

        // locate the bin containing the remK-th largest (unique boundary)
        if (t < 256) {
            unsigned int S = s_suf[t], Sn = s_suf[t + 1];
            if (S >= remK && Sn < remK) { s_bin = t; s_high = Sn; }
        }
        __syncthreads();
        pref = (pref << 8) | (unsigned int)s_bin;
        remK -= s_high;
    }
    const unsigned long long thresh = pref;  // == the 80th-largest key exactly

    // ---- collect the exactly-80 keys >= threshold -------------------------
    if (t == 0) s_cnt = 0;
    if (t < 128) cand[t] = 0ULL;
    __syncthreads();
#pragma unroll
    for (int e = 0; e < 8; e++) {
        if (key[e] >= thresh) {
            unsigned int pos = atomicAdd(&s_cnt, 1u);
            if (pos < 128) cand[pos] = key[e];
        }
    }
    __syncthreads();

    // ---- bitonic sort 128 slots, descending (pads are 0 -> sink) ----------
    for (int k = 2; k <= 128; k <<= 1) {
        for (int j = k >> 1; j > 0; j >>= 1) {
            if (t < 128) {
                int ixj = t ^ j;
                if (ixj > t) {
                    unsigned long long a = cand[t], c2 = cand[ixj];
                    bool desc = ((t & k) == 0);
                    if (desc ? (a < c2) : (a > c2)) { cand[t] = c2; cand[ixj] = a; }
                }
            }
            __syncthreads();
        }
    }

    // ---- scalar outputs + smem index table --------------------------------
    const size_t O1 = (size_t)BB * KK * DD;       // pred_s_e
    const size_t O2 = O1 + (size_t)BB * KK * 2;   // offset_gt_list
    const size_t O3 = O2 + (size_t)BB * KK * 2;   // pred_score

    if (t < KK) {
        int idx = (NN - 1) - (int)(cand[t] & 0xFFFu);
        s_idx[t] = idx;
        int row = idx >> 6;
        int col = idx & 63;
        int blk = b * KK + t;
        out[O1 + blk * 2 + 0] = (float)row;
        out[O1 + blk * 2 + 1] = (float)(col + 1);
        float2 og = ((const float2*)offset_gt)[(size_t)b * NN + idx];
        ((float2*)(out + O2))[blk] = og;
        out[O3 + blk] = tmap[(size_t)b * NN + idx];
    }
    __syncthreads();

    // ---- row gather: 80 rows x 512 f32, warp-per-row, float4 streams ------
    for (int p = warp; p < KK; p += 16) {        // 5 rows per warp
        const int idx = s_idx[p];
        const float4* __restrict__ src =
            (const float4*)(map2d + ((size_t)b * NN + idx) * DD);
        float4* __restrict__ dst =
            (float4*)(out + ((size_t)(b * KK + p)) * DD);
#pragma unroll
        for (int v = 0; v < 4; v++)               // 128 float4 per row
            dst[lane + v * 32] = src[lane + v * 32];
    }
}

extern "C" void kernel_launch(void* const* d_in, const int* in_sizes, int n_in,
                              void* d_out, int out_size) {
    const float* selection_logit = (const float*)d_in[0];
    const float* map2d           = (const float*)d_in[1];
    const float* offset_gt       = (const float*)d_in[2];
    const float* tmap            = (const float*)d_in[3];
    float* out = (float*)d_out;

    proposal_kernel<<<BB, 512>>>(selection_logit, map2d, offset_gt, tmap, out);
}

// round 9
// speedup vs baseline: 3.7646x; 2.1080x over previous
#include <cuda_runtime.h>
#include <stdint.h>

#define BB 32
#define TT 64
#define NN 4096   // TT*TT
#define KK 80
#define DD 512

// topk flat indices handoff (no device allocation allowed -> __device__ global)
__device__ int g_topk_idx[BB * KK];

// ---------------------------------------------------------------------------
// Kernel 1: per-batch exact top-80.
//  - 4-pass radix select (8-bit digits) over 32-bit monotone float keys,
//    keys held in registers (4/thread @ 1024 threads).
//  - candidates (u >= u_80th) collected to smem, then ordered by
//    rank-counting on the full 44-bit key (float || 4095-idx) -> exact
//    jax.lax.top_k descending order with stable smaller-idx tie-break.
//  - writes g_topk_idx + the three scalar output sections.
// ---------------------------------------------------------------------------
__global__ __launch_bounds__(1024, 1)
void select_kernel(const float* __restrict__ logit,
                   const float* __restrict__ offset_gt,
                   const float* __restrict__ tmap,
                   float* __restrict__ out) {
    __shared__ unsigned int       hist[256];
    __shared__ unsigned int       s_suf[257];   // suffix sums; s_suf[256]=0
    __shared__ unsigned int       s_warp[8];
    __shared__ unsigned long long cand[128];
    __shared__ unsigned int       s_cnt;
    __shared__ int                s_bin;
    __shared__ unsigned int       s_high;

    const int b    = blockIdx.x;
    const int t    = threadIdx.x;
    const int lane = t & 31;
    const int warp = t >> 5;

    // ---- encode 4 monotone 32-bit keys per thread -------------------------
    unsigned int key[4];
    const float* base = logit + (size_t)b * NN;
#pragma unroll
    for (int e = 0; e < 4; e++) {
        float v = base[t + e * 1024];
        unsigned int u;
        if (v == 0.0f) {
            u = 0u;  // masked (-inf)
        } else {
            u = __float_as_uint(v);
            u = (u & 0x80000000u) ? ~u : (u | 0x80000000u);  // monotone map
        }
        key[e] = u;
    }

    // ---- 4-pass radix select of the 80th-largest u (with duplicates) ------
    unsigned int pref = 0;   // resolved high bits (right-aligned)
    unsigned int remK = KK;

    for (int pass = 0; pass < 4; pass++) {
        const int shift = 24 - pass * 8;

        if (t < 256) hist[t] = 0;
        if (t == 256) s_suf[256] = 0;
        __syncthreads();                                   // hist zeroed

        // warp-aggregated histogram of matching keys' current digit
#pragma unroll
        for (int e = 0; e < 4; e++) {
            bool m = (pass == 0) || ((key[e] >> (shift + 8)) == pref);
            unsigned int d = (key[e] >> shift) & 255u;
            unsigned int mv = __ballot_sync(0xffffffffu, m);
            if (m) {
                unsigned int peers = __match_any_sync(mv, d);
                if (lane == (__ffs(peers) - 1))
                    atomicAdd(&hist[d], (unsigned int)__popc(peers));
            }
        }
        __syncthreads();                                   // hist complete

        // inclusive suffix scan: s_suf[d] = sum_{j>=d} hist[j]
        // (warps 0..7 fully cover t<256 -> full-warp shfl is safe)
        unsigned int s = (t < 256) ? hist[t] : 0u;
#pragma unroll
        for (int off = 1; off < 32; off <<= 1) {
            unsigned int o = __shfl_down_sync(0xffffffffu, s, off);
            if (lane + off < 32) s += o;
        }
        if (t < 256 && lane == 0) s_warp[warp] = s;
        __syncthreads();                                   // s_warp visible
        if (t < 256) {
            unsigned int hi = 0;
#pragma unroll
            for (int w2 = 0; w2 < 8; w2++)
                if (w2 > warp) hi += s_warp[w2];
            s_suf[t] = s + hi;
        }
        __syncthreads();                                   // s_suf visible

        // unique boundary bin: s_suf[bin] >= remK > s_suf[bin+1]
        if (t < 256) {
            unsigned int S = s_suf[t], Sn = s_suf[t + 1];
            if (S >= remK && Sn < remK) { s_bin = t; s_high = Sn; }
        }
        __syncthreads();                                   // s_bin visible

        pref = (pref << 8) | (unsigned int)s_bin;
        remK -= s_high;
    }
    const unsigned int uth = pref;  // exact 32-bit value of the 80th-largest

    // ---- collect candidates (u >= uth) with 44-bit tie-break keys ---------
    if (t == 0) s_cnt = 0;
    if (t < 128) cand[t] = 0ULL;
    __syncthreads();
#pragma unroll
    for (int e = 0; e < 4; e++) {
        if (key[e] >= uth) {
            int i = t + e * 1024;
            unsigned int pos = atomicAdd(&s_cnt, 1u);
            if (pos < 128)
                cand[pos] = ((unsigned long long)key[e] << 12)
                          | (unsigned int)(NN - 1 - i);
        }
    }
    __syncthreads();

    // ---- order by rank-counting (distinct 44-bit keys; pads=0 sink) -------
    if (t < 128) {
        const unsigned long long k = cand[t];
        int rank = 0;
#pragma unroll 8
        for (int j = 0; j < 128; j++)
            rank += (cand[j] > k);           // broadcast smem reads

        if (k != 0ULL && rank < KK) {
            const int idx = (NN - 1) - (int)(k & 0xFFFu);
            const int row = idx >> 6;
            const int col = idx & 63;
            const int blk = b * KK + rank;

            g_topk_idx[blk] = idx;

            const size_t O1 = (size_t)BB * KK * DD;       // pred_s_e
            const size_t O2 = O1 + (size_t)BB * KK * 2;   // offset_gt_list
            const size_t O3 = O2 + (size_t)BB * KK * 2;   // pred_score

            out[O1 + blk * 2 + 0] = (float)row;
            out[O1 + blk * 2 + 1] = (float)(col + 1);
            float2 og = ((const float2*)offset_gt)[(size_t)b * NN + idx];
            ((float2*)(out + O2))[blk] = og;
            out[O3 + blk] = tmap[(size_t)b * NN + idx];
        }
    }
}

// ---------------------------------------------------------------------------
// Kernel 2: full-chip row gather. One block per (b,k): 64 threads x 2
// independent float4 copies (both loads issued before stores -> MLP=2).
// ---------------------------------------------------------------------------
__global__ __launch_bounds__(64)
void gather_kernel(const float* __restrict__ map2d,
                   float* __restrict__ out) {
    const int blk = blockIdx.x;            // 0 .. B*K-1
    const int b   = blk / KK;
    const int t   = threadIdx.x;           // 0..63

    const int idx = g_topk_idx[blk];

    const float4* __restrict__ src =
        (const float4*)(map2d + ((size_t)b * NN + idx) * DD);
    float4* __restrict__ dst = (float4*)(out + (size_t)blk * DD);

    float4 x = src[t];
    float4 y = src[t + 64];
    dst[t]      = x;
    dst[t + 64] = y;
}

extern "C" void kernel_launch(void* const* d_in, const int* in_sizes, int n_in,
                              void* d_out, int out_size) {
    const float* selection_logit = (const float*)d_in[0];
    const float* map2d           = (const float*)d_in[1];
    const float* offset_gt       = (const float*)d_in[2];
    const float* tmap            = (const float*)d_in[3];
    float* out = (float*)d_out;

    select_kernel<<<BB, 1024>>>(selection_logit, offset_gt, tmap, out);
    gather_kernel<<<BB * KK, 64>>>(map2d, out);
}